// round 12
// baseline (speedup 1.0000x reference)
#include <cuda_runtime.h>
#include <cuda_fp16.h>
#include <cstdint>

#define Nn   100000
#define Ee   1600000
#define Dd   64
#define HIDv 512
#define C3   192
#define NBLKP 196                  // prep blocks (512 threads each; 196*512 = 100352 >= Nn)
#define TPB  512
#define STATS_BLOCKS 148
#define GM_BLOCKS 128
#define KT 32
#define PADS 36

// ---------------- device scratch ----------------
__device__ __align__(16) __half g_uah[Nn * Dd];   // fp16 u ping
__device__ __align__(16) __half g_ubh[Nn * Dd];   // fp16 u pong
__device__ __align__(16) float g_H[(size_t)Nn * C3];
__device__ float g_norm[Nn];
__device__ float g_norm2[Nn];
__device__ int   g_deg[Nn];
__device__ int   g_rowptr[Nn + 1];
__device__ int   g_cursor[Nn];
__device__ int   g_csr[Ee];
__device__ int   g_bsum[512];
__device__ int   g_barcnt[8];
__device__ __align__(16) float g_G[HIDv * C3];
__device__ float g_bterm[HIDv];
__device__ __align__(16) float g_Cpart[(size_t)STATS_BLOCKS * C3 * C3];
__device__ float g_mHpart[STATS_BLOCKS * C3];
__device__ __align__(16) float g_Cmat[C3 * C3];
__device__ float g_mH[C3];
__device__ float g_scale[HIDv];
__device__ float g_shift[HIDv];
__device__ __align__(16) float g_W2[C3 * Dd];
__device__ __align__(16) float g_c0[Dd];

__device__ __forceinline__ float tf32r(float x) {
    uint32_t u;
    asm("cvt.rna.tf32.f32 %0, %1;" : "=r"(u) : "f"(x));
    return __uint_as_float(u);
}
__device__ __forceinline__ uint32_t f2u(float x) { return __float_as_uint(x); }

__device__ __forceinline__ void mma_tf32(float4& d, uint32_t a0, uint32_t a1, uint32_t a2, uint32_t a3,
                                         uint32_t b0, uint32_t b1) {
    asm volatile(
        "mma.sync.aligned.m16n8k8.row.col.f32.tf32.tf32.f32 "
        "{%0,%1,%2,%3}, {%4,%5,%6,%7}, {%8,%9}, {%0,%1,%2,%3};"
        : "+f"(d.x), "+f"(d.y), "+f"(d.z), "+f"(d.w)
        : "r"(a0), "r"(a1), "r"(a2), "r"(a3), "r"(b0), "r"(b1));
}

// software global barrier; all `target` blocks co-resident
__device__ __forceinline__ void gbarN(int k, int target) {
    __syncthreads();
    if (threadIdx.x == 0) {
        __threadfence();
        atomicAdd(&g_barcnt[k], 1);
        while (*(volatile int*)&g_barcnt[k] < target) { }
        __threadfence();
    }
    __syncthreads();
}

__device__ __forceinline__ void hillis512(int* sh, int t) {
#pragma unroll
    for (int off = 1; off < 512; off <<= 1) {
        int x = (t >= off) ? sh[t - off] : 0;
        __syncthreads();
        sh[t] += x;
        __syncthreads();
    }
}

// ---------------- kernel 1: fused zero + count + scan + norm + scale + csr (196x512) ----------------
__global__ __launch_bounds__(TPB) void prep(const int* __restrict__ src,
                                            const int* __restrict__ dst,
                                            const float* __restrict__ feats) {
    __shared__ int sh[TPB];
    __shared__ float snorm[TPB];
    int b = blockIdx.x, t = threadIdx.x;
    int i = b * TPB + t;

    // phase Z: zero degree array
    for (int idx = i; idx < Nn; idx += NBLKP * TPB) g_deg[idx] = 0;
    gbarN(0, NBLKP);

    // phase A0: degree histogram
    for (int e = i; e < Ee; e += NBLKP * TPB)
        atomicAdd(&g_deg[dst[e]], 1);
    gbarN(1, NBLKP);

    // phase A: block-local exclusive scan of degrees
    int v = (i < Nn) ? g_deg[i] : 0;
    sh[t] = v;
    __syncthreads();
    hillis512(sh, t);
    int excl = sh[t] - v;
    if (t == TPB - 1) g_bsum[b] = sh[TPB - 1];
    gbarN(2, NBLKP);

    // phase B: block 0 scans the 196 block sums
    if (b == 0) {
        int v1 = (t < NBLKP) ? *(volatile int*)&g_bsum[t] : 0;
        sh[t] = v1;
        __syncthreads();
        hillis512(sh, t);
        if (t < NBLKP) g_bsum[t] = sh[t] - v1;
    }
    gbarN(3, NBLKP);

    // phase C: finalize rowptr/cursor/norm, scale features -> fp16 u0
    int boff = *(volatile int*)&g_bsum[b];
    float nm = 0.f;
    if (i < Nn) {
        int r = excl + boff;
        g_rowptr[i] = r;
        g_cursor[i] = r;
        float f = (v < 1) ? 1.0f : (float)v;
        nm = rsqrtf(f);
        g_norm[i] = nm;
        g_norm2[i] = nm * nm;
        if (i == Nn - 1) g_rowptr[Nn] = Ee;
    }
    snorm[t] = nm;
    __syncthreads();
    int base = b * TPB;
    int nnode = min(TPB, Nn - base);
    if (nnode > 0) {
        const float4* f4 = (const float4*)feats;
        uint2* u2 = (uint2*)g_uah;
        for (int idx = t; idx < nnode * 16; idx += TPB) {
            float4 vv = f4[(size_t)base * 16 + idx];
            float s = snorm[idx >> 4];
            __half2 h0 = __float22half2_rn(make_float2(vv.x * s, vv.y * s));
            __half2 h1 = __float22half2_rn(make_float2(vv.z * s, vv.w * s));
            uint2 w;
            w.x = *(uint32_t*)&h0;
            w.y = *(uint32_t*)&h1;
            u2[(size_t)base * 16 + idx] = w;
        }
    }
    gbarN(4, NBLKP);

    // phase D: CSR fill
    for (int e = i; e < Ee; e += NBLKP * TPB) {
        int d = dst[e];
        int p = atomicAdd(&g_cursor[d], 1);
        g_csr[p] = src[e];
    }
}

// ---------------- SpMM: half-warp per node, fp16 gathers (128B/edge), exact fp32 adds ----------------
__device__ __forceinline__ void acc_h4(float4& a, uint2 v) {
    float2 lo = __half22float2(*(__half2*)&v.x);
    float2 hi = __half22float2(*(__half2*)&v.y);
    a.x += lo.x; a.y += lo.y; a.z += hi.x; a.w += hi.y;
}

__global__ __launch_bounds__(256) void spmm(int srcbuf, int jcol, int writeU) {
    int node = (blockIdx.x << 4) | (threadIdx.x >> 4);   // half-warp id
    int q = threadIdx.x & 15;                            // lane within half
    int hbase = threadIdx.x & 16;
    const uint2* __restrict__ uin = (const uint2*)(srcbuf ? g_ubh : g_uah);
    uint2* __restrict__ uout = (uint2*)(srcbuf ? g_uah : g_ubh);
    int beg = g_rowptr[node];
    int end = g_rowptr[node + 1];
    float4 accA = make_float4(0.f, 0.f, 0.f, 0.f);
    float4 accB = make_float4(0.f, 0.f, 0.f, 0.f);
    int i = beg;
    for (; i + 8 <= end; i += 8) {
        int cv = g_csr[i + (q & 7)];
        int s0 = __shfl_sync(0xffffffffu, cv, hbase + 0);
        int s1 = __shfl_sync(0xffffffffu, cv, hbase + 1);
        int s2 = __shfl_sync(0xffffffffu, cv, hbase + 2);
        int s3 = __shfl_sync(0xffffffffu, cv, hbase + 3);
        int s4 = __shfl_sync(0xffffffffu, cv, hbase + 4);
        int s5 = __shfl_sync(0xffffffffu, cv, hbase + 5);
        int s6 = __shfl_sync(0xffffffffu, cv, hbase + 6);
        int s7 = __shfl_sync(0xffffffffu, cv, hbase + 7);
        uint2 v0 = uin[s0 * 16 + q];
        uint2 v1 = uin[s1 * 16 + q];
        uint2 v2 = uin[s2 * 16 + q];
        uint2 v3 = uin[s3 * 16 + q];
        uint2 v4 = uin[s4 * 16 + q];
        uint2 v5 = uin[s5 * 16 + q];
        uint2 v6 = uin[s6 * 16 + q];
        uint2 v7 = uin[s7 * 16 + q];
        acc_h4(accA, v0); acc_h4(accA, v1); acc_h4(accA, v2); acc_h4(accA, v3);
        acc_h4(accB, v4); acc_h4(accB, v5); acc_h4(accB, v6); acc_h4(accB, v7);
    }
    // tail: <8 edges
    if (i < end) {
        int cv = g_csr[min(i + (q & 7), end - 1)];
        int nrem = end - i;
#pragma unroll
        for (int e = 0; e < 7; e++) {
            int s = __shfl_sync(0xffffffffu, cv, hbase + e);
            if (e < nrem) {
                uint2 v = uin[s * 16 + q];
                acc_h4(accA, v);
            }
        }
    }
    accA.x += accB.x; accA.y += accB.y; accA.z += accB.z; accA.w += accB.w;
    float nm = g_norm[node];
    float4 h;
    h.x = tf32r(accA.x * nm); h.y = tf32r(accA.y * nm);
    h.z = tf32r(accA.z * nm); h.w = tf32r(accA.w * nm);
    ((float4*)g_H)[(size_t)node * 48 + jcol * 16 + q] = h;
    if (writeU) {
        float n2 = g_norm2[node];
        __half2 h0 = __float22half2_rn(make_float2(accA.x * n2, accA.y * n2));
        __half2 h1 = __float22half2_rn(make_float2(accA.z * n2, accA.w * n2));
        uint2 w;
        w.x = *(uint32_t*)&h0;
        w.y = *(uint32_t*)&h1;
        uout[node * 16 + q] = w;
    }
}

// ---------------- combined: blocks [0,128) gmat+bterm, [128,276) stats via tf32 mma ----------------
union ShGS {
    struct { float Hs[C3 * PADS]; float mred[384]; } st;
    struct { float fw[4 * 1536]; float red[384]; } gm;
};

__global__ __launch_bounds__(384, 1) void gstats(const float* __restrict__ fcW,
                                                 const float* __restrict__ w0,
                                                 const float* __restrict__ w1,
                                                 const float* __restrict__ w2,
                                                 const float* __restrict__ fcb,
                                                 const float* __restrict__ b0,
                                                 const float* __restrict__ b1,
                                                 const float* __restrict__ b2) {
    __shared__ ShGS sh;
    int tid = threadIdx.x;

    if (blockIdx.x < GM_BLOCKS) {
        float* fw = sh.gm.fw;
        float* red = sh.gm.red;
        int hb = blockIdx.x * 4;
        for (int i = tid; i < 4 * 1536; i += 384)
            fw[i] = fcW[(size_t)hb * 1536 + i];
        __syncthreads();
        for (int i = tid; i < 4 * 192; i += 384) {
            int hl = i / 192, c = i % 192, j = c >> 6, d = c & 63;
            const float* W = (j == 0) ? w0 : (j == 1) ? w1 : w2;
            const float* f = fw + hl * 1536 + j * 512;
            float acc = 0.f;
#pragma unroll 8
            for (int m = 0; m < 512; m++) acc = fmaf(f[m], W[m * 64 + d], acc);
            g_G[(hb + hl) * C3 + c] = acc;
        }
        for (int r = 0; r < 4; r++) {
            float p = 0.f;
            for (int m = tid; m < 1536; m += 384) {
                float bv = (m < 512) ? b0[m] : (m < 1024) ? b1[m - 512] : b2[m - 1024];
                p = fmaf(fw[r * 1536 + m], bv, p);
            }
            red[tid] = p;
            __syncthreads();
            if (tid < 128) red[tid] += red[tid + 128] + red[tid + 256];
            __syncthreads();
            for (int s = 64; s > 0; s >>= 1) {
                if (tid < s) red[tid] += red[tid + s];
                __syncthreads();
            }
            if (tid == 0) g_bterm[hb + r] = red[0] + fcb[hb + r];
            __syncthreads();
        }
        return;
    }

    int sb = blockIdx.x - GM_BLOCKS;
    float* Hs = sh.st.Hs;
    float* mred = sh.st.mred;
    int warp = tid >> 5, lane = tid & 31;
    int mg = warp >> 1, ng = warp & 1;
    int lr = lane >> 2, lc = lane & 3;

    float4 acc[2][12];
#pragma unroll
    for (int a = 0; a < 2; a++)
#pragma unroll
        for (int b = 0; b < 12; b++) acc[a][b] = make_float4(0.f, 0.f, 0.f, 0.f);
    float msum = 0.f;

    int cfix = tid % C3;
    int rbase = tid / C3;

    const int ntiles = Nn / KT;
    for (int tile = sb; tile < ntiles; tile += STATS_BLOCKS) {
        int r0 = tile * KT;
        __syncthreads();
#pragma unroll
        for (int i = 0; i < KT / 2; i++) {
            int r = rbase + 2 * i;
            float v = g_H[(size_t)(r0 + r) * C3 + cfix];
            Hs[cfix * PADS + r] = v;
            msum += v;
        }
        __syncthreads();
#pragma unroll
        for (int ks = 0; ks < KT / 8; ks++) {
            int k0 = ks * 8;
            uint32_t a[2][4];
#pragma unroll
            for (int mt = 0; mt < 2; mt++) {
                int m = mg * 32 + mt * 16;
                a[mt][0] = f2u(Hs[(m + lr) * PADS + k0 + lc]);
                a[mt][1] = f2u(Hs[(m + 8 + lr) * PADS + k0 + lc]);
                a[mt][2] = f2u(Hs[(m + lr) * PADS + k0 + lc + 4]);
                a[mt][3] = f2u(Hs[(m + 8 + lr) * PADS + k0 + lc + 4]);
            }
#pragma unroll
            for (int nt = 0; nt < 12; nt++) {
                int n = ng * 96 + nt * 8;
                uint32_t b0v = f2u(Hs[(n + lr) * PADS + k0 + lc]);
                uint32_t b1v = f2u(Hs[(n + lr) * PADS + k0 + lc + 4]);
                mma_tf32(acc[0][nt], a[0][0], a[0][1], a[0][2], a[0][3], b0v, b1v);
                mma_tf32(acc[1][nt], a[1][0], a[1][1], a[1][2], a[1][3], b0v, b1v);
            }
        }
    }

    float* cp = g_Cpart + (size_t)sb * (C3 * C3);
#pragma unroll
    for (int mt = 0; mt < 2; mt++)
#pragma unroll
        for (int nt = 0; nt < 12; nt++) {
            int row = mg * 32 + mt * 16 + lr;
            int col = ng * 96 + nt * 8 + 2 * lc;
            float4 v = acc[mt][nt];
            *(float2*)&cp[(size_t)row * C3 + col] = make_float2(v.x, v.y);
            *(float2*)&cp[(size_t)(row + 8) * C3 + col] = make_float2(v.z, v.w);
        }
    mred[tid] = msum;
    __syncthreads();
    if (tid < C3) g_mHpart[sb * C3 + tid] = mred[tid] + mred[tid + C3];
}

// ---------------- fused: reduce_stats -> bnprep -> w2c0 ----------------
__global__ __launch_bounds__(192) void postk(const float* __restrict__ gamma,
                                             const float* __restrict__ beta,
                                             const float* __restrict__ q) {
    int b = blockIdx.x, c = threadIdx.x;
    int gt = b * 192 + c;
    const float invN = 1.0f / (float)Nn;

    for (int idx = gt; idx < C3 * C3; idx += GM_BLOCKS * 192) {
        float s = 0.f;
        for (int p = 0; p < STATS_BLOCKS; p++) s += g_Cpart[(size_t)p * (C3 * C3) + idx];
        g_Cmat[idx] = s * invN;
    }
    if (b == 0) {
        float s = 0.f;
        for (int p = 0; p < STATS_BLOCKS; p++) s += g_mHpart[p * C3 + c];
        g_mH[c] = s * invN;
    }
    gbarN(5, GM_BLOCKS);

    {
        __shared__ float gsh[4][C3];
        __shared__ float red[C3], red2[C3];
        int hb = b * 4;
#pragma unroll
        for (int j = 0; j < 4; j++) gsh[j][c] = g_G[(hb + j) * C3 + c];
        __syncthreads();
        float t0 = 0.f, t1 = 0.f, t2 = 0.f, t3 = 0.f;
        for (int cc = 0; cc < C3; cc++) {
            float cm = g_Cmat[cc * C3 + c];
            t0 = fmaf(cm, gsh[0][cc], t0);
            t1 = fmaf(cm, gsh[1][cc], t1);
            t2 = fmaf(cm, gsh[2][cc], t2);
            t3 = fmaf(cm, gsh[3][cc], t3);
        }
        float mh = g_mH[c];
        float ts[4] = {t0, t1, t2, t3};
#pragma unroll
        for (int j = 0; j < 4; j++) {
            __syncthreads();
            red[c]  = gsh[j][c] * ts[j];
            red2[c] = gsh[j][c] * mh;
            __syncthreads();
            if (c < 64) {
                red[c]  += red[c + 64]  + red[c + 128];
                red2[c] += red2[c + 64] + red2[c + 128];
            }
            __syncthreads();
            for (int s = 32; s > 0; s >>= 1) {
                if (c < s) { red[c] += red[c + s]; red2[c] += red2[c + s]; }
                __syncthreads();
            }
            if (c == 0) {
                int h = hb + j;
                float quad = red[0], dot1 = red2[0], bt = g_bterm[h];
                float mu  = dot1 + bt;
                float ef2 = quad + 2.f * bt * dot1 + bt * bt;
                float var = ef2 - mu * mu;
                float sc  = rsqrtf(var + 1e-5f) * gamma[h];
                g_scale[h] = sc;
                g_shift[h] = beta[h] - mu * sc;
            }
        }
    }
    gbarN(6, GM_BLOCKS);

    if (gt < C3 * Dd) {
        int o = gt & 63, cc = gt >> 6;
        float s = 0.f;
#pragma unroll
        for (int k = 0; k < 8; k++) {
            int h = k * 64 + o;
            s += q[k] * g_scale[h] * g_G[h * C3 + cc];
        }
        g_W2[cc * Dd + o] = tf32r(s);
    }
    if (gt < Dd) {
        float s = 0.f;
#pragma unroll
        for (int k = 0; k < 8; k++) {
            int h = k * 64 + gt;
            s += q[k] * (g_scale[h] * g_bterm[h] + g_shift[h]);
        }
        g_c0[gt] = s;
    }
}

// ---------------- out = H (Nx192) @ W2^T via tf32 mma ----------------
#define PH 68
#define PW 72
__global__ __launch_bounds__(256) void out_mma(float* __restrict__ out) {
    if (blockIdx.x == 0 && threadIdx.x < 8) g_barcnt[threadIdx.x] = 0;

    __shared__ float Hs[64 * PH];
    __shared__ float W2s[64 * PW];
    int tid = threadIdx.x;
    int warp = tid >> 5, lane = tid & 31;
    int mg = warp >> 1, ng = warp & 1;
    int lr = lane >> 2, lc = lane & 3;
    int r0 = blockIdx.x * 64;
    int nr = min(64, Nn - r0);

    float4 acc[4];
#pragma unroll
    for (int a = 0; a < 4; a++) acc[a] = make_float4(0.f, 0.f, 0.f, 0.f);

#pragma unroll
    for (int kc = 0; kc < 3; kc++) {
        __syncthreads();
#pragma unroll
        for (int i = 0; i < 4; i++) {
            int idx4 = tid + i * 256;
            int m = idx4 >> 4, k4 = (idx4 & 15) << 2;
            float4 v = make_float4(0.f, 0.f, 0.f, 0.f);
            if (m < nr) v = *(const float4*)&g_H[(size_t)(r0 + m) * C3 + kc * 64 + k4];
            *(float4*)&Hs[m * PH + k4] = v;
        }
#pragma unroll
        for (int i = 0; i < 4; i++) {
            int idx4 = tid + i * 256;
            int k = idx4 >> 4, n4 = (idx4 & 15) << 2;
            *(float4*)&W2s[k * PW + n4] = *(const float4*)&g_W2[(kc * 64 + k) * Dd + n4];
        }
        __syncthreads();
#pragma unroll
        for (int ks = 0; ks < 8; ks++) {
            int k0 = ks * 8;
            int m0 = mg * 16;
            uint32_t a0 = f2u(Hs[(m0 + lr) * PH + k0 + lc]);
            uint32_t a1 = f2u(Hs[(m0 + 8 + lr) * PH + k0 + lc]);
            uint32_t a2 = f2u(Hs[(m0 + lr) * PH + k0 + lc + 4]);
            uint32_t a3 = f2u(Hs[(m0 + 8 + lr) * PH + k0 + lc + 4]);
#pragma unroll
            for (int nt = 0; nt < 4; nt++) {
                int n0 = ng * 32 + nt * 8;
                uint32_t b0 = f2u(W2s[(k0 + lc) * PW + n0 + lr]);
                uint32_t b1 = f2u(W2s[(k0 + lc + 4) * PW + n0 + lr]);
                mma_tf32(acc[nt], a0, a1, a2, a3, b0, b1);
            }
        }
    }

#pragma unroll
    for (int nt = 0; nt < 4; nt++) {
        int row = mg * 16 + lr;
        int col = ng * 32 + nt * 8 + 2 * lc;
        float2 cc = *(const float2*)&g_c0[col];
        float4 v = acc[nt];
        if (row < nr)
            *(float2*)&out[(size_t)(r0 + row) * Dd + col] = make_float2(v.x + cc.x, v.y + cc.y);
        if (row + 8 < nr)
            *(float2*)&out[(size_t)(r0 + row + 8) * Dd + col] = make_float2(v.z + cc.x, v.w + cc.y);
    }
}

// ---------------- launch ----------------
extern "C" void kernel_launch(void* const* d_in, const int* in_sizes, int n_in,
                              void* d_out, int out_size) {
    const float* feats = (const float*)d_in[0];
    const int*   src   = (const int*)d_in[1];
    const int*   dst   = (const int*)d_in[2];
    const float* W0    = (const float*)d_in[3];
    const float* b0    = (const float*)d_in[4];
    const float* W1    = (const float*)d_in[5];
    const float* b1    = (const float*)d_in[6];
    const float* W2w   = (const float*)d_in[7];
    const float* b2    = (const float*)d_in[8];
    const float* fcW   = (const float*)d_in[9];
    const float* fcb   = (const float*)d_in[10];
    const float* gamma = (const float*)d_in[11];
    const float* beta  = (const float*)d_in[12];
    const float* q     = (const float*)d_in[13];
    float* out = (float*)d_out;

    prep<<<NBLKP, TPB>>>(src, dst, feats);                         // launch 1
    spmm<<<Nn / 16, 256>>>(0, 0, 1);                               // launch 2
    spmm<<<Nn / 16, 256>>>(1, 1, 1);                               // launch 3
    spmm<<<Nn / 16, 256>>>(0, 2, 0);                               // launch 4
    gstats<<<GM_BLOCKS + STATS_BLOCKS, 384>>>(fcW, W0, W1, W2w, fcb, b0, b1, b2); // 5
    postk<<<GM_BLOCKS, 192>>>(gamma, beta, q);                     // launch 6
    out_mma<<<(Nn + 63) / 64, 256>>>(out);                         // launch 7
}

// round 14
// speedup vs baseline: 1.1422x; 1.1422x over previous
#include <cuda_runtime.h>
#include <cuda_fp16.h>
#include <cstdint>

#define Nn   100000
#define Ee   1600000
#define Dd   64
#define HIDv 512
#define C3   192
#define NBLK1 ((Nn + 255) / 256)   // 391
#define STATS_BLOCKS 148
#define GM_BLOCKS 128
#define KT 32
#define PADS 36

// ---------------- device scratch ----------------
__device__ __align__(16) __half g_uah[Nn * Dd];   // fp16 u ping
__device__ __align__(16) __half g_ubh[Nn * Dd];   // fp16 u pong
__device__ __align__(16) float g_H[(size_t)Nn * C3];
__device__ float g_norm[Nn];
__device__ float g_norm2[Nn];
__device__ int   g_deg[Nn];
__device__ int   g_rowptr[Nn + 1];
__device__ int   g_cursor[Nn];
__device__ int   g_csr[Ee];
__device__ int   g_bsum[512];
__device__ int   g_barcnt[8];
__device__ __align__(16) float g_G[HIDv * C3];
__device__ float g_bterm[HIDv];
__device__ __align__(16) float g_Cpart[(size_t)STATS_BLOCKS * C3 * C3];
__device__ float g_mHpart[STATS_BLOCKS * C3];
__device__ __align__(16) float g_Cmat[C3 * C3];
__device__ float g_mH[C3];
__device__ float g_scale[HIDv];
__device__ float g_shift[HIDv];
__device__ __align__(16) float g_W2[C3 * Dd];
__device__ __align__(16) float g_c0[Dd];

__device__ __forceinline__ float tf32r(float x) {
    uint32_t u;
    asm("cvt.rna.tf32.f32 %0, %1;" : "=r"(u) : "f"(x));
    return __uint_as_float(u);
}
__device__ __forceinline__ uint32_t f2u(float x) { return __float_as_uint(x); }

__device__ __forceinline__ void mma_tf32(float4& d, uint32_t a0, uint32_t a1, uint32_t a2, uint32_t a3,
                                         uint32_t b0, uint32_t b1) {
    asm volatile(
        "mma.sync.aligned.m16n8k8.row.col.f32.tf32.tf32.f32 "
        "{%0,%1,%2,%3}, {%4,%5,%6,%7}, {%8,%9}, {%0,%1,%2,%3};"
        : "+f"(d.x), "+f"(d.y), "+f"(d.z), "+f"(d.w)
        : "r"(a0), "r"(a1), "r"(a2), "r"(a3), "r"(b0), "r"(b1));
}

// software global barrier; all `target` blocks co-resident
__device__ __forceinline__ void gbarN(int k, int target) {
    __syncthreads();
    if (threadIdx.x == 0) {
        __threadfence();
        atomicAdd(&g_barcnt[k], 1);
        while (*(volatile int*)&g_barcnt[k] < target) { }
        __threadfence();
    }
    __syncthreads();
}

__device__ __forceinline__ void hillis256(int* sh, int t) {
#pragma unroll
    for (int off = 1; off < 256; off <<= 1) {
        int x = (t >= off) ? sh[t - off] : 0;
        __syncthreads();
        sh[t] += x;
        __syncthreads();
    }
}

// ---------------- kernel 1: blocks [0,391) prep; blocks [391,519) gmat+bterm ----------------
__global__ __launch_bounds__(256) void prep(const int* __restrict__ src,
                                            const int* __restrict__ dst,
                                            const float* __restrict__ feats,
                                            const float* __restrict__ fcW,
                                            const float* __restrict__ w0,
                                            const float* __restrict__ w1,
                                            const float* __restrict__ w2,
                                            const float* __restrict__ fcb,
                                            const float* __restrict__ b0,
                                            const float* __restrict__ b1,
                                            const float* __restrict__ b2) {
    int t = threadIdx.x;

    if (blockIdx.x >= NBLK1) {
        // ---- gmat + bterm for 4 h-rows (independent of graph work; overlaps prep) ----
        __shared__ float fw[4 * 1536];
        __shared__ float red[256];
        int hb = (blockIdx.x - NBLK1) * 4;
        for (int i = t; i < 4 * 1536; i += 256)
            fw[i] = fcW[(size_t)hb * 1536 + i];
        __syncthreads();
        for (int i = t; i < 4 * 192; i += 256) {
            int hl = i / 192, c = i % 192, j = c >> 6, d = c & 63;
            const float* W = (j == 0) ? w0 : (j == 1) ? w1 : w2;
            const float* f = fw + hl * 1536 + j * 512;
            float acc = 0.f;
#pragma unroll 8
            for (int m = 0; m < 512; m++) acc = fmaf(f[m], W[m * 64 + d], acc);
            g_G[(hb + hl) * C3 + c] = acc;
        }
        for (int r = 0; r < 4; r++) {
            float p = 0.f;
            for (int m = t; m < 1536; m += 256) {
                float bv = (m < 512) ? b0[m] : (m < 1024) ? b1[m - 512] : b2[m - 1024];
                p = fmaf(fw[r * 1536 + m], bv, p);
            }
            red[t] = p;
            __syncthreads();
            for (int s = 128; s > 0; s >>= 1) {
                if (t < s) red[t] += red[t + s];
                __syncthreads();
            }
            if (t == 0) g_bterm[hb + r] = red[0] + fcb[hb + r];
            __syncthreads();
        }
        return;
    }

    // ---- graph preprocessing (391 blocks, soft barriers among themselves only) ----
    __shared__ int sh[256];
    __shared__ float snorm[256];
    int b = blockIdx.x;
    int i = b * 256 + t;

    for (int idx = i; idx < Nn; idx += NBLK1 * 256) g_deg[idx] = 0;
    gbarN(0, NBLK1);

    for (int e = i; e < Ee; e += NBLK1 * 256)
        atomicAdd(&g_deg[dst[e]], 1);
    gbarN(1, NBLK1);

    int v = (i < Nn) ? g_deg[i] : 0;
    sh[t] = v;
    __syncthreads();
    hillis256(sh, t);
    int excl = sh[t] - v;
    if (t == 255) g_bsum[b] = sh[255];
    gbarN(2, NBLK1);

    if (b == 0) {
        int v1 = *(volatile int*)&g_bsum[t];
        sh[t] = v1;
        __syncthreads();
        hillis256(sh, t);
        int s1 = sh[t];
        int tot1 = sh[255];
        __syncthreads();
        int v2 = (t + 256 < NBLK1) ? *(volatile int*)&g_bsum[t + 256] : 0;
        sh[t] = v2;
        __syncthreads();
        hillis256(sh, t);
        int s2 = sh[t] + tot1;
        __syncthreads();
        g_bsum[t] = s1 - v1;
        if (t + 256 < NBLK1) g_bsum[t + 256] = s2 - v2;
    }
    gbarN(3, NBLK1);

    int boff = *(volatile int*)&g_bsum[b];
    float nm = 0.f;
    if (i < Nn) {
        int r = excl + boff;
        g_rowptr[i] = r;
        g_cursor[i] = r;
        float f = (v < 1) ? 1.0f : (float)v;
        nm = rsqrtf(f);
        g_norm[i] = nm;
        g_norm2[i] = nm * nm;
        if (i == Nn - 1) g_rowptr[Nn] = Ee;
    }
    snorm[t] = nm;
    __syncthreads();
    int base = b * 256;
    int nnode = min(256, Nn - base);
    if (nnode > 0) {
        const float4* f4 = (const float4*)feats;
        uint2* u2 = (uint2*)g_uah;
        for (int idx = t; idx < nnode * 16; idx += 256) {
            float4 vv = f4[(size_t)base * 16 + idx];
            float s = snorm[idx >> 4];
            __half2 h0 = __float22half2_rn(make_float2(vv.x * s, vv.y * s));
            __half2 h1 = __float22half2_rn(make_float2(vv.z * s, vv.w * s));
            uint2 w;
            w.x = *(uint32_t*)&h0;
            w.y = *(uint32_t*)&h1;
            u2[(size_t)base * 16 + idx] = w;
        }
    }
    gbarN(4, NBLK1);

    for (int e = i; e < Ee; e += NBLK1 * 256) {
        int d = dst[e];
        int p = atomicAdd(&g_cursor[d], 1);
        g_csr[p] = src[e];
    }
}

// ---------------- SpMM: half-warp per node, BROADCAST index loads (no shfl), fp16 gathers ----------------
__device__ __forceinline__ void acc_h4(float4& a, uint2 v) {
    float2 lo = __half22float2(*(__half2*)&v.x);
    float2 hi = __half22float2(*(__half2*)&v.y);
    a.x += lo.x; a.y += lo.y; a.z += hi.x; a.w += hi.y;
}

__global__ __launch_bounds__(256) void spmm(int srcbuf, int jcol, int writeU) {
    int node = (blockIdx.x << 4) | (threadIdx.x >> 4);   // half-warp id
    int q = threadIdx.x & 15;                            // lane within half
    const uint2* __restrict__ uin = (const uint2*)(srcbuf ? g_ubh : g_uah);
    uint2* __restrict__ uout = (uint2*)(srcbuf ? g_uah : g_ubh);
    const int* __restrict__ csr = g_csr;
    int beg = g_rowptr[node];
    int end = g_rowptr[node + 1];
    float4 accA = make_float4(0.f, 0.f, 0.f, 0.f);
    float4 accB = make_float4(0.f, 0.f, 0.f, 0.f);
    int i = beg;
    for (; i + 8 <= end; i += 8) {
        // broadcast loads: same address across the half-warp, consecutive words share sectors
        int s0 = csr[i + 0];
        int s1 = csr[i + 1];
        int s2 = csr[i + 2];
        int s3 = csr[i + 3];
        int s4 = csr[i + 4];
        int s5 = csr[i + 5];
        int s6 = csr[i + 6];
        int s7 = csr[i + 7];
        uint2 v0 = uin[s0 * 16 + q];
        uint2 v1 = uin[s1 * 16 + q];
        uint2 v2 = uin[s2 * 16 + q];
        uint2 v3 = uin[s3 * 16 + q];
        uint2 v4 = uin[s4 * 16 + q];
        uint2 v5 = uin[s5 * 16 + q];
        uint2 v6 = uin[s6 * 16 + q];
        uint2 v7 = uin[s7 * 16 + q];
        acc_h4(accA, v0); acc_h4(accA, v1); acc_h4(accA, v2); acc_h4(accA, v3);
        acc_h4(accB, v4); acc_h4(accB, v5); acc_h4(accB, v6); acc_h4(accB, v7);
    }
    // tail: <8 edges, independent predicated loads
    if (i < end) {
        int nrem = end - i;
#pragma unroll
        for (int e = 0; e < 7; e++) {
            if (e < nrem) {
                int s = csr[i + e];
                uint2 v = uin[s * 16 + q];
                acc_h4(accA, v);
            }
        }
    }
    accA.x += accB.x; accA.y += accB.y; accA.z += accB.z; accA.w += accB.w;
    float nm = g_norm[node];
    float4 h;
    h.x = tf32r(accA.x * nm); h.y = tf32r(accA.y * nm);
    h.z = tf32r(accA.z * nm); h.w = tf32r(accA.w * nm);
    ((float4*)g_H)[(size_t)node * 48 + jcol * 16 + q] = h;
    if (writeU) {
        float n2 = g_norm2[node];
        __half2 h0 = __float22half2_rn(make_float2(accA.x * n2, accA.y * n2));
        __half2 h1 = __float22half2_rn(make_float2(accA.z * n2, accA.w * n2));
        uint2 w;
        w.x = *(uint32_t*)&h0;
        w.y = *(uint32_t*)&h1;
        uout[node * 16 + q] = w;
    }
}

// ---------------- stats via tf32 mma (148 blocks) ----------------
__global__ __launch_bounds__(384, 1) void stats_mma() {
    __shared__ float Hs[C3 * PADS];
    __shared__ float mred[384];
    int tid = threadIdx.x;
    int sb = blockIdx.x;
    int warp = tid >> 5, lane = tid & 31;
    int mg = warp >> 1, ng = warp & 1;
    int lr = lane >> 2, lc = lane & 3;

    float4 acc[2][12];
#pragma unroll
    for (int a = 0; a < 2; a++)
#pragma unroll
        for (int b = 0; b < 12; b++) acc[a][b] = make_float4(0.f, 0.f, 0.f, 0.f);
    float msum = 0.f;

    int cfix = tid % C3;
    int rbase = tid / C3;

    const int ntiles = Nn / KT;
    for (int tile = sb; tile < ntiles; tile += STATS_BLOCKS) {
        int r0 = tile * KT;
        __syncthreads();
#pragma unroll
        for (int i = 0; i < KT / 2; i++) {
            int r = rbase + 2 * i;
            float v = g_H[(size_t)(r0 + r) * C3 + cfix];
            Hs[cfix * PADS + r] = v;
            msum += v;
        }
        __syncthreads();
#pragma unroll
        for (int ks = 0; ks < KT / 8; ks++) {
            int k0 = ks * 8;
            uint32_t a[2][4];
#pragma unroll
            for (int mt = 0; mt < 2; mt++) {
                int m = mg * 32 + mt * 16;
                a[mt][0] = f2u(Hs[(m + lr) * PADS + k0 + lc]);
                a[mt][1] = f2u(Hs[(m + 8 + lr) * PADS + k0 + lc]);
                a[mt][2] = f2u(Hs[(m + lr) * PADS + k0 + lc + 4]);
                a[mt][3] = f2u(Hs[(m + 8 + lr) * PADS + k0 + lc + 4]);
            }
#pragma unroll
            for (int nt = 0; nt < 12; nt++) {
                int n = ng * 96 + nt * 8;
                uint32_t b0v = f2u(Hs[(n + lr) * PADS + k0 + lc]);
                uint32_t b1v = f2u(Hs[(n + lr) * PADS + k0 + lc + 4]);
                mma_tf32(acc[0][nt], a[0][0], a[0][1], a[0][2], a[0][3], b0v, b1v);
                mma_tf32(acc[1][nt], a[1][0], a[1][1], a[1][2], a[1][3], b0v, b1v);
            }
        }
    }

    float* cp = g_Cpart + (size_t)sb * (C3 * C3);
#pragma unroll
    for (int mt = 0; mt < 2; mt++)
#pragma unroll
        for (int nt = 0; nt < 12; nt++) {
            int row = mg * 32 + mt * 16 + lr;
            int col = ng * 96 + nt * 8 + 2 * lc;
            float4 v = acc[mt][nt];
            *(float2*)&cp[(size_t)row * C3 + col] = make_float2(v.x, v.y);
            *(float2*)&cp[(size_t)(row + 8) * C3 + col] = make_float2(v.z, v.w);
        }
    mred[tid] = msum;
    __syncthreads();
    if (tid < C3) g_mHpart[sb * C3 + tid] = mred[tid] + mred[tid + C3];
}

// ---------------- fused: reduce_stats -> bnprep -> w2c0 ----------------
__global__ __launch_bounds__(192) void postk(const float* __restrict__ gamma,
                                             const float* __restrict__ beta,
                                             const float* __restrict__ q) {
    int b = blockIdx.x, c = threadIdx.x;
    int gt = b * 192 + c;
    const float invN = 1.0f / (float)Nn;

    for (int idx = gt; idx < C3 * C3; idx += GM_BLOCKS * 192) {
        float s = 0.f;
        for (int p = 0; p < STATS_BLOCKS; p++) s += g_Cpart[(size_t)p * (C3 * C3) + idx];
        g_Cmat[idx] = s * invN;
    }
    if (b == 0) {
        float s = 0.f;
        for (int p = 0; p < STATS_BLOCKS; p++) s += g_mHpart[p * C3 + c];
        g_mH[c] = s * invN;
    }
    gbarN(5, GM_BLOCKS);

    {
        __shared__ float gsh[4][C3];
        __shared__ float red[C3], red2[C3];
        int hb = b * 4;
#pragma unroll
        for (int j = 0; j < 4; j++) gsh[j][c] = g_G[(hb + j) * C3 + c];
        __syncthreads();
        float t0 = 0.f, t1 = 0.f, t2 = 0.f, t3 = 0.f;
        for (int cc = 0; cc < C3; cc++) {
            float cm = g_Cmat[cc * C3 + c];
            t0 = fmaf(cm, gsh[0][cc], t0);
            t1 = fmaf(cm, gsh[1][cc], t1);
            t2 = fmaf(cm, gsh[2][cc], t2);
            t3 = fmaf(cm, gsh[3][cc], t3);
        }
        float mh = g_mH[c];
        float ts[4] = {t0, t1, t2, t3};
#pragma unroll
        for (int j = 0; j < 4; j++) {
            __syncthreads();
            red[c]  = gsh[j][c] * ts[j];
            red2[c] = gsh[j][c] * mh;
            __syncthreads();
            if (c < 64) {
                red[c]  += red[c + 64]  + red[c + 128];
                red2[c] += red2[c + 64] + red2[c + 128];
            }
            __syncthreads();
            for (int s = 32; s > 0; s >>= 1) {
                if (c < s) { red[c] += red[c + s]; red2[c] += red2[c + s]; }
                __syncthreads();
            }
            if (c == 0) {
                int h = hb + j;
                float quad = red[0], dot1 = red2[0], bt = g_bterm[h];
                float mu  = dot1 + bt;
                float ef2 = quad + 2.f * bt * dot1 + bt * bt;
                float var = ef2 - mu * mu;
                float sc  = rsqrtf(var + 1e-5f) * gamma[h];
                g_scale[h] = sc;
                g_shift[h] = beta[h] - mu * sc;
            }
        }
    }
    gbarN(6, GM_BLOCKS);

    if (gt < C3 * Dd) {
        int o = gt & 63, cc = gt >> 6;
        float s = 0.f;
#pragma unroll
        for (int k = 0; k < 8; k++) {
            int h = k * 64 + o;
            s += q[k] * g_scale[h] * g_G[h * C3 + cc];
        }
        g_W2[cc * Dd + o] = tf32r(s);
    }
    if (gt < Dd) {
        float s = 0.f;
#pragma unroll
        for (int k = 0; k < 8; k++) {
            int h = k * 64 + gt;
            s += q[k] * (g_scale[h] * g_bterm[h] + g_shift[h]);
        }
        g_c0[gt] = s;
    }
}

// ---------------- out = H (Nx192) @ W2^T via tf32 mma ----------------
#define PH 68
#define PW 72
__global__ __launch_bounds__(256) void out_mma(float* __restrict__ out) {
    if (blockIdx.x == 0 && threadIdx.x < 8) g_barcnt[threadIdx.x] = 0;

    __shared__ float Hs[64 * PH];
    __shared__ float W2s[64 * PW];
    int tid = threadIdx.x;
    int warp = tid >> 5, lane = tid & 31;
    int mg = warp >> 1, ng = warp & 1;
    int lr = lane >> 2, lc = lane & 3;
    int r0 = blockIdx.x * 64;
    int nr = min(64, Nn - r0);

    float4 acc[4];
#pragma unroll
    for (int a = 0; a < 4; a++) acc[a] = make_float4(0.f, 0.f, 0.f, 0.f);

#pragma unroll
    for (int kc = 0; kc < 3; kc++) {
        __syncthreads();
#pragma unroll
        for (int i = 0; i < 4; i++) {
            int idx4 = tid + i * 256;
            int m = idx4 >> 4, k4 = (idx4 & 15) << 2;
            float4 v = make_float4(0.f, 0.f, 0.f, 0.f);
            if (m < nr) v = *(const float4*)&g_H[(size_t)(r0 + m) * C3 + kc * 64 + k4];
            *(float4*)&Hs[m * PH + k4] = v;
        }
#pragma unroll
        for (int i = 0; i < 4; i++) {
            int idx4 = tid + i * 256;
            int k = idx4 >> 4, n4 = (idx4 & 15) << 2;
            *(float4*)&W2s[k * PW + n4] = *(const float4*)&g_W2[(kc * 64 + k) * Dd + n4];
        }
        __syncthreads();
#pragma unroll
        for (int ks = 0; ks < 8; ks++) {
            int k0 = ks * 8;
            int m0 = mg * 16;
            uint32_t a0 = f2u(Hs[(m0 + lr) * PH + k0 + lc]);
            uint32_t a1 = f2u(Hs[(m0 + 8 + lr) * PH + k0 + lc]);
            uint32_t a2 = f2u(Hs[(m0 + lr) * PH + k0 + lc + 4]);
            uint32_t a3 = f2u(Hs[(m0 + 8 + lr) * PH + k0 + lc + 4]);
#pragma unroll
            for (int nt = 0; nt < 4; nt++) {
                int n0 = ng * 32 + nt * 8;
                uint32_t b0 = f2u(W2s[(k0 + lc) * PW + n0 + lr]);
                uint32_t b1 = f2u(W2s[(k0 + lc + 4) * PW + n0 + lr]);
                mma_tf32(acc[nt], a0, a1, a2, a3, b0, b1);
            }
        }
    }

#pragma unroll
    for (int nt = 0; nt < 4; nt++) {
        int row = mg * 16 + lr;
        int col = ng * 32 + nt * 8 + 2 * lc;
        float2 cc = *(const float2*)&g_c0[col];
        float4 v = acc[nt];
        if (row < nr)
            *(float2*)&out[(size_t)(r0 + row) * Dd + col] = make_float2(v.x + cc.x, v.y + cc.y);
        if (row + 8 < nr)
            *(float2*)&out[(size_t)(r0 + row + 8) * Dd + col] = make_float2(v.z + cc.x, v.w + cc.y);
    }
}

// ---------------- launch ----------------
extern "C" void kernel_launch(void* const* d_in, const int* in_sizes, int n_in,
                              void* d_out, int out_size) {
    const float* feats = (const float*)d_in[0];
    const int*   src   = (const int*)d_in[1];
    const int*   dst   = (const int*)d_in[2];
    const float* W0    = (const float*)d_in[3];
    const float* b0    = (const float*)d_in[4];
    const float* W1    = (const float*)d_in[5];
    const float* b1    = (const float*)d_in[6];
    const float* W2w   = (const float*)d_in[7];
    const float* b2    = (const float*)d_in[8];
    const float* fcW   = (const float*)d_in[9];
    const float* fcb   = (const float*)d_in[10];
    const float* gamma = (const float*)d_in[11];
    const float* beta  = (const float*)d_in[12];
    const float* q     = (const float*)d_in[13];
    float* out = (float*)d_out;

    prep<<<NBLK1 + GM_BLOCKS, 256>>>(src, dst, feats,
                                     fcW, W0, W1, W2w, fcb, b0, b1, b2);  // launch 1 (prep ∥ gmat)
    spmm<<<Nn / 16, 256>>>(0, 0, 1);                                      // launch 2
    spmm<<<Nn / 16, 256>>>(1, 1, 1);                                      // launch 3
    spmm<<<Nn / 16, 256>>>(0, 2, 0);                                      // launch 4
    stats_mma<<<STATS_BLOCKS, 384>>>();                                   // launch 5
    postk<<<GM_BLOCKS, 192>>>(gamma, beta, q);                            // launch 6
    out_mma<<<(Nn + 63) / 64, 256>>>(out);                                // launch 7
}

// round 15
// speedup vs baseline: 1.1926x; 1.0441x over previous
#include <cuda_runtime.h>
#include <cuda_fp16.h>
#include <cstdint>

#define Nn   100000
#define Ee   1600000
#define Dd   64
#define HIDv 512
#define C3   192
#define NBLK1 ((Nn + 255) / 256)   // 391
#define STATS_BLOCKS 148
#define GM_BLOCKS 128
#define KT 32
#define PADS 36

// ---------------- device scratch ----------------
__device__ __align__(16) __half g_uah[Nn * Dd];   // fp16 u ping
__device__ __align__(16) __half g_ubh[Nn * Dd];   // fp16 u pong
__device__ __align__(16) __half g_Hh[(size_t)Nn * C3];   // fp16 H
__device__ float g_norm[Nn];
__device__ float g_norm2[Nn];
__device__ int   g_deg[Nn];
__device__ int   g_rowptr[Nn + 1];
__device__ int   g_cursor[Nn];
__device__ int   g_csr[Ee];
__device__ int   g_bsum[512];
__device__ int   g_barcnt[8];
__device__ __align__(16) float g_G[HIDv * C3];
__device__ float g_bterm[HIDv];
__device__ __align__(16) float g_Cpart[(size_t)STATS_BLOCKS * C3 * C3];
__device__ float g_mHpart[STATS_BLOCKS * C3];
__device__ __align__(16) float g_Cmat[C3 * C3];
__device__ float g_mH[C3];
__device__ float g_scale[HIDv];
__device__ float g_shift[HIDv];
__device__ __align__(16) float g_W2[C3 * Dd];
__device__ __align__(16) float g_c0[Dd];

__device__ __forceinline__ float tf32r(float x) {
    uint32_t u;
    asm("cvt.rna.tf32.f32 %0, %1;" : "=r"(u) : "f"(x));
    return __uint_as_float(u);
}
__device__ __forceinline__ uint32_t f2u(float x) { return __float_as_uint(x); }

__device__ __forceinline__ void mma_tf32(float4& d, uint32_t a0, uint32_t a1, uint32_t a2, uint32_t a3,
                                         uint32_t b0, uint32_t b1) {
    asm volatile(
        "mma.sync.aligned.m16n8k8.row.col.f32.tf32.tf32.f32 "
        "{%0,%1,%2,%3}, {%4,%5,%6,%7}, {%8,%9}, {%0,%1,%2,%3};"
        : "+f"(d.x), "+f"(d.y), "+f"(d.z), "+f"(d.w)
        : "r"(a0), "r"(a1), "r"(a2), "r"(a3), "r"(b0), "r"(b1));
}

// software global barrier; all `target` blocks co-resident
__device__ __forceinline__ void gbarN(int k, int target) {
    __syncthreads();
    if (threadIdx.x == 0) {
        __threadfence();
        atomicAdd(&g_barcnt[k], 1);
        while (*(volatile int*)&g_barcnt[k] < target) { }
        __threadfence();
    }
    __syncthreads();
}

__device__ __forceinline__ void hillis256(int* sh, int t) {
#pragma unroll
    for (int off = 1; off < 256; off <<= 1) {
        int x = (t >= off) ? sh[t - off] : 0;
        __syncthreads();
        sh[t] += x;
        __syncthreads();
    }
}

// ---------------- kernel 1: blocks [0,391) prep; blocks [391,519) gmat+bterm ----------------
__global__ __launch_bounds__(256) void prep(const int* __restrict__ src,
                                            const int* __restrict__ dst,
                                            const float* __restrict__ feats,
                                            const float* __restrict__ fcW,
                                            const float* __restrict__ w0,
                                            const float* __restrict__ w1,
                                            const float* __restrict__ w2,
                                            const float* __restrict__ fcb,
                                            const float* __restrict__ b0,
                                            const float* __restrict__ b1,
                                            const float* __restrict__ b2) {
    int t = threadIdx.x;

    if (blockIdx.x >= NBLK1) {
        // ---- gmat + bterm for 4 h-rows (independent; overlaps prep) ----
        __shared__ float fw[4 * 1536];
        __shared__ float red[256];
        int hb = (blockIdx.x - NBLK1) * 4;
        for (int i = t; i < 4 * 1536; i += 256)
            fw[i] = fcW[(size_t)hb * 1536 + i];
        __syncthreads();
        for (int i = t; i < 4 * 192; i += 256) {
            int hl = i / 192, c = i % 192, j = c >> 6, d = c & 63;
            const float* W = (j == 0) ? w0 : (j == 1) ? w1 : w2;
            const float* f = fw + hl * 1536 + j * 512;
            float acc = 0.f;
#pragma unroll 8
            for (int m = 0; m < 512; m++) acc = fmaf(f[m], W[m * 64 + d], acc);
            g_G[(hb + hl) * C3 + c] = acc;
        }
        for (int r = 0; r < 4; r++) {
            float p = 0.f;
            for (int m = t; m < 1536; m += 256) {
                float bv = (m < 512) ? b0[m] : (m < 1024) ? b1[m - 512] : b2[m - 1024];
                p = fmaf(fw[r * 1536 + m], bv, p);
            }
            red[t] = p;
            __syncthreads();
            for (int s = 128; s > 0; s >>= 1) {
                if (t < s) red[t] += red[t + s];
                __syncthreads();
            }
            if (t == 0) g_bterm[hb + r] = red[0] + fcb[hb + r];
            __syncthreads();
        }
        return;
    }

    // ---- graph preprocessing (391 blocks) ----
    __shared__ int sh[256];
    __shared__ float snorm[256];
    int b = blockIdx.x;
    int i = b * 256 + t;

    for (int idx = i; idx < Nn; idx += NBLK1 * 256) g_deg[idx] = 0;
    gbarN(0, NBLK1);

    for (int e = i; e < Ee; e += NBLK1 * 256)
        atomicAdd(&g_deg[dst[e]], 1);
    gbarN(1, NBLK1);

    int v = (i < Nn) ? g_deg[i] : 0;
    sh[t] = v;
    __syncthreads();
    hillis256(sh, t);
    int excl = sh[t] - v;
    if (t == 255) g_bsum[b] = sh[255];
    gbarN(2, NBLK1);

    if (b == 0) {
        int v1 = *(volatile int*)&g_bsum[t];
        sh[t] = v1;
        __syncthreads();
        hillis256(sh, t);
        int s1 = sh[t];
        int tot1 = sh[255];
        __syncthreads();
        int v2 = (t + 256 < NBLK1) ? *(volatile int*)&g_bsum[t + 256] : 0;
        sh[t] = v2;
        __syncthreads();
        hillis256(sh, t);
        int s2 = sh[t] + tot1;
        __syncthreads();
        g_bsum[t] = s1 - v1;
        if (t + 256 < NBLK1) g_bsum[t + 256] = s2 - v2;
    }
    gbarN(3, NBLK1);

    int boff = *(volatile int*)&g_bsum[b];
    float nm = 0.f;
    if (i < Nn) {
        int r = excl + boff;
        g_rowptr[i] = r;
        g_cursor[i] = r;
        float f = (v < 1) ? 1.0f : (float)v;
        nm = rsqrtf(f);
        g_norm[i] = nm;
        g_norm2[i] = nm * nm;
        if (i == Nn - 1) g_rowptr[Nn] = Ee;
    }
    snorm[t] = nm;
    __syncthreads();
    int base = b * 256;
    int nnode = min(256, Nn - base);
    if (nnode > 0) {
        const float4* f4 = (const float4*)feats;
        uint2* u2 = (uint2*)g_uah;
        for (int idx = t; idx < nnode * 16; idx += 256) {
            float4 vv = f4[(size_t)base * 16 + idx];
            float s = snorm[idx >> 4];
            __half2 h0 = __float22half2_rn(make_float2(vv.x * s, vv.y * s));
            __half2 h1 = __float22half2_rn(make_float2(vv.z * s, vv.w * s));
            uint2 w;
            w.x = *(uint32_t*)&h0;
            w.y = *(uint32_t*)&h1;
            u2[(size_t)base * 16 + idx] = w;
        }
    }
    gbarN(4, NBLK1);

    for (int e = i; e < Ee; e += NBLK1 * 256) {
        int d = dst[e];
        int p = atomicAdd(&g_cursor[d], 1);
        g_csr[p] = src[e];
    }
}

// ---------------- SpMM: half-warp per node, broadcast index loads, fp16 gathers + fp16 H writes ----------------
__device__ __forceinline__ void acc_h4(float4& a, uint2 v) {
    float2 lo = __half22float2(*(__half2*)&v.x);
    float2 hi = __half22float2(*(__half2*)&v.y);
    a.x += lo.x; a.y += lo.y; a.z += hi.x; a.w += hi.y;
}

__global__ __launch_bounds__(256) void spmm(int srcbuf, int jcol, int writeU) {
    int node = (blockIdx.x << 4) | (threadIdx.x >> 4);   // half-warp id
    int q = threadIdx.x & 15;                            // lane within half
    const uint2* __restrict__ uin = (const uint2*)(srcbuf ? g_ubh : g_uah);
    uint2* __restrict__ uout = (uint2*)(srcbuf ? g_uah : g_ubh);
    const int* __restrict__ csr = g_csr;
    int beg = g_rowptr[node];
    int end = g_rowptr[node + 1];
    float4 accA = make_float4(0.f, 0.f, 0.f, 0.f);
    float4 accB = make_float4(0.f, 0.f, 0.f, 0.f);
    int i = beg;
    for (; i + 8 <= end; i += 8) {
        int s0 = csr[i + 0];
        int s1 = csr[i + 1];
        int s2 = csr[i + 2];
        int s3 = csr[i + 3];
        int s4 = csr[i + 4];
        int s5 = csr[i + 5];
        int s6 = csr[i + 6];
        int s7 = csr[i + 7];
        uint2 v0 = uin[s0 * 16 + q];
        uint2 v1 = uin[s1 * 16 + q];
        uint2 v2 = uin[s2 * 16 + q];
        uint2 v3 = uin[s3 * 16 + q];
        uint2 v4 = uin[s4 * 16 + q];
        uint2 v5 = uin[s5 * 16 + q];
        uint2 v6 = uin[s6 * 16 + q];
        uint2 v7 = uin[s7 * 16 + q];
        acc_h4(accA, v0); acc_h4(accA, v1); acc_h4(accA, v2); acc_h4(accA, v3);
        acc_h4(accB, v4); acc_h4(accB, v5); acc_h4(accB, v6); acc_h4(accB, v7);
    }
    if (i < end) {
        int nrem = end - i;
#pragma unroll
        for (int e = 0; e < 7; e++) {
            if (e < nrem) {
                int s = csr[i + e];
                uint2 v = uin[s * 16 + q];
                acc_h4(accA, v);
            }
        }
    }
    accA.x += accB.x; accA.y += accB.y; accA.z += accB.z; accA.w += accB.w;
    float nm = g_norm[node];
    __half2 p0 = __float22half2_rn(make_float2(accA.x * nm, accA.y * nm));
    __half2 p1 = __float22half2_rn(make_float2(accA.z * nm, accA.w * nm));
    uint2 hw;
    hw.x = *(uint32_t*)&p0;
    hw.y = *(uint32_t*)&p1;
    ((uint2*)g_Hh)[(size_t)node * 48 + jcol * 16 + q] = hw;
    if (writeU) {
        float n2 = g_norm2[node];
        __half2 u0 = __float22half2_rn(make_float2(accA.x * n2, accA.y * n2));
        __half2 u1 = __float22half2_rn(make_float2(accA.z * n2, accA.w * n2));
        uint2 w;
        w.x = *(uint32_t*)&u0;
        w.y = *(uint32_t*)&u1;
        uout[node * 16 + q] = w;
    }
}

// ---------------- stats via tf32 mma + fused reduce/bnprep/w2c0 (148 blocks, 384 thr) ----------------
__global__ __launch_bounds__(384, 1) void statspost(const float* __restrict__ gamma,
                                                    const float* __restrict__ beta,
                                                    const float* __restrict__ q) {
    __shared__ float Hs[C3 * PADS];
    __shared__ float mred[384];
    __shared__ float gsh[4][C3];
    __shared__ float red[C3], red2[C3];

    int tid = threadIdx.x;
    int sb = blockIdx.x;
    int warp = tid >> 5, lane = tid & 31;
    int mg = warp >> 1, ng = warp & 1;
    int lr = lane >> 2, lc = lane & 3;

    float4 acc[2][12];
#pragma unroll
    for (int a = 0; a < 2; a++)
#pragma unroll
        for (int b = 0; b < 12; b++) acc[a][b] = make_float4(0.f, 0.f, 0.f, 0.f);
    float msum = 0.f;

    int cfix = tid % C3;
    int rbase = tid / C3;

    const int ntiles = Nn / KT;
    for (int tile = sb; tile < ntiles; tile += STATS_BLOCKS) {
        int r0 = tile * KT;
        __syncthreads();
#pragma unroll
        for (int i = 0; i < KT / 2; i++) {
            int r = rbase + 2 * i;
            float v = __half2float(g_Hh[(size_t)(r0 + r) * C3 + cfix]);
            Hs[cfix * PADS + r] = v;
            msum += v;
        }
        __syncthreads();
#pragma unroll
        for (int ks = 0; ks < KT / 8; ks++) {
            int k0 = ks * 8;
            uint32_t a[2][4];
#pragma unroll
            for (int mt = 0; mt < 2; mt++) {
                int m = mg * 32 + mt * 16;
                a[mt][0] = f2u(Hs[(m + lr) * PADS + k0 + lc]);
                a[mt][1] = f2u(Hs[(m + 8 + lr) * PADS + k0 + lc]);
                a[mt][2] = f2u(Hs[(m + lr) * PADS + k0 + lc + 4]);
                a[mt][3] = f2u(Hs[(m + 8 + lr) * PADS + k0 + lc + 4]);
            }
#pragma unroll
            for (int nt = 0; nt < 12; nt++) {
                int n = ng * 96 + nt * 8;
                uint32_t b0v = f2u(Hs[(n + lr) * PADS + k0 + lc]);
                uint32_t b1v = f2u(Hs[(n + lr) * PADS + k0 + lc + 4]);
                mma_tf32(acc[0][nt], a[0][0], a[0][1], a[0][2], a[0][3], b0v, b1v);
                mma_tf32(acc[1][nt], a[1][0], a[1][1], a[1][2], a[1][3], b0v, b1v);
            }
        }
    }

    float* cp = g_Cpart + (size_t)sb * (C3 * C3);
#pragma unroll
    for (int mt = 0; mt < 2; mt++)
#pragma unroll
        for (int nt = 0; nt < 12; nt++) {
            int row = mg * 32 + mt * 16 + lr;
            int col = ng * 96 + nt * 8 + 2 * lc;
            float4 v = acc[mt][nt];
            *(float2*)&cp[(size_t)row * C3 + col] = make_float2(v.x, v.y);
            *(float2*)&cp[(size_t)(row + 8) * C3 + col] = make_float2(v.z, v.w);
        }
    mred[tid] = msum;
    __syncthreads();
    if (tid < C3) g_mHpart[sb * C3 + tid] = mred[tid] + mred[tid + C3];

    // ---- barrier: all 148 blocks' partials visible ----
    gbarN(5, STATS_BLOCKS);

    // ---- phase 1: reduce partials ----
    const float invN = 1.0f / (float)Nn;
    int gt = sb * 384 + tid;
    for (int idx = gt; idx < C3 * C3; idx += STATS_BLOCKS * 384) {
        float s = 0.f;
        for (int p = 0; p < STATS_BLOCKS; p++) s += g_Cpart[(size_t)p * (C3 * C3) + idx];
        g_Cmat[idx] = s * invN;
    }
    if (sb == 0 && tid < C3) {
        float s = 0.f;
        for (int p = 0; p < STATS_BLOCKS; p++) s += g_mHpart[p * C3 + tid];
        g_mH[tid] = s * invN;
    }
    gbarN(6, STATS_BLOCKS);

    // ---- phase 2: bnprep (blocks 0..127, 4 h-rows each) ----
    if (sb < GM_BLOCKS) {
        int c = tid;
        int hb = sb * 4;
        if (c < C3) {
#pragma unroll
            for (int j = 0; j < 4; j++) gsh[j][c] = g_G[(hb + j) * C3 + c];
        }
        __syncthreads();
        float t0 = 0.f, t1 = 0.f, t2 = 0.f, t3 = 0.f, mh = 0.f;
        if (c < C3) {
            for (int cc = 0; cc < C3; cc++) {
                float cm = g_Cmat[cc * C3 + c];
                t0 = fmaf(cm, gsh[0][cc], t0);
                t1 = fmaf(cm, gsh[1][cc], t1);
                t2 = fmaf(cm, gsh[2][cc], t2);
                t3 = fmaf(cm, gsh[3][cc], t3);
            }
            mh = g_mH[c];
        }
        float ts[4] = {t0, t1, t2, t3};
#pragma unroll
        for (int j = 0; j < 4; j++) {
            __syncthreads();
            if (c < C3) {
                red[c]  = gsh[j][c] * ts[j];
                red2[c] = gsh[j][c] * mh;
            }
            __syncthreads();
            if (c < 64) {
                red[c]  += red[c + 64]  + red[c + 128];
                red2[c] += red2[c + 64] + red2[c + 128];
            }
            __syncthreads();
            for (int s = 32; s > 0; s >>= 1) {
                if (c < s) { red[c] += red[c + s]; red2[c] += red2[c + s]; }
                __syncthreads();
            }
            if (c == 0) {
                int h = hb + j;
                float quad = red[0], dot1 = red2[0], bt = g_bterm[h];
                float mu  = dot1 + bt;
                float ef2 = quad + 2.f * bt * dot1 + bt * bt;
                float var = ef2 - mu * mu;
                float sc  = rsqrtf(var + 1e-5f) * gamma[h];
                g_scale[h] = sc;
                g_shift[h] = beta[h] - mu * sc;
            }
        }
    }
    gbarN(7, STATS_BLOCKS);

    // ---- phase 3: w2c0 ----
    if (gt < C3 * Dd) {
        int o = gt & 63, cc = gt >> 6;
        float s = 0.f;
#pragma unroll
        for (int k = 0; k < 8; k++) {
            int h = k * 64 + o;
            s += q[k] * g_scale[h] * g_G[h * C3 + cc];
        }
        g_W2[cc * Dd + o] = tf32r(s);
    }
    if (gt < Dd) {
        float s = 0.f;
#pragma unroll
        for (int k = 0; k < 8; k++) {
            int h = k * 64 + gt;
            s += q[k] * (g_scale[h] * g_bterm[h] + g_shift[h]);
        }
        g_c0[gt] = s;
    }
}

// ---------------- out = H (Nx192, fp16) @ W2^T via tf32 mma ----------------
#define PH 68
#define PW 72
__global__ __launch_bounds__(256) void out_mma(float* __restrict__ out) {
    if (blockIdx.x == 0 && threadIdx.x < 8) g_barcnt[threadIdx.x] = 0;

    __shared__ float Hs[64 * PH];
    __shared__ float W2s[64 * PW];
    int tid = threadIdx.x;
    int warp = tid >> 5, lane = tid & 31;
    int mg = warp >> 1, ng = warp & 1;
    int lr = lane >> 2, lc = lane & 3;
    int r0 = blockIdx.x * 64;
    int nr = min(64, Nn - r0);

    float4 acc[4];
#pragma unroll
    for (int a = 0; a < 4; a++) acc[a] = make_float4(0.f, 0.f, 0.f, 0.f);

#pragma unroll
    for (int kc = 0; kc < 3; kc++) {
        __syncthreads();
#pragma unroll
        for (int i = 0; i < 4; i++) {
            int idx4 = tid + i * 256;
            int m = idx4 >> 4, k4 = (idx4 & 15) << 2;
            float4 v = make_float4(0.f, 0.f, 0.f, 0.f);
            if (m < nr) {
                uint2 hv = ((const uint2*)g_Hh)[((size_t)(r0 + m) * C3 + kc * 64 + k4) >> 2];
                float2 lo = __half22float2(*(__half2*)&hv.x);
                float2 hi = __half22float2(*(__half2*)&hv.y);
                v = make_float4(lo.x, lo.y, hi.x, hi.y);
            }
            *(float4*)&Hs[m * PH + k4] = v;
        }
#pragma unroll
        for (int i = 0; i < 4; i++) {
            int idx4 = tid + i * 256;
            int k = idx4 >> 4, n4 = (idx4 & 15) << 2;
            *(float4*)&W2s[k * PW + n4] = *(const float4*)&g_W2[(kc * 64 + k) * Dd + n4];
        }
        __syncthreads();
#pragma unroll
        for (int ks = 0; ks < 8; ks++) {
            int k0 = ks * 8;
            int m0 = mg * 16;
            uint32_t a0 = f2u(Hs[(m0 + lr) * PH + k0 + lc]);
            uint32_t a1 = f2u(Hs[(m0 + 8 + lr) * PH + k0 + lc]);
            uint32_t a2 = f2u(Hs[(m0 + lr) * PH + k0 + lc + 4]);
            uint32_t a3 = f2u(Hs[(m0 + 8 + lr) * PH + k0 + lc + 4]);
#pragma unroll
            for (int nt = 0; nt < 4; nt++) {
                int n0 = ng * 32 + nt * 8;
                uint32_t b0 = f2u(W2s[(k0 + lc) * PW + n0 + lr]);
                uint32_t b1 = f2u(W2s[(k0 + lc + 4) * PW + n0 + lr]);
                mma_tf32(acc[nt], a0, a1, a2, a3, b0, b1);
            }
        }
    }

#pragma unroll
    for (int nt = 0; nt < 4; nt++) {
        int row = mg * 16 + lr;
        int col = ng * 32 + nt * 8 + 2 * lc;
        float2 cc = *(const float2*)&g_c0[col];
        float4 v = acc[nt];
        if (row < nr)
            *(float2*)&out[(size_t)(r0 + row) * Dd + col] = make_float2(v.x + cc.x, v.y + cc.y);
        if (row + 8 < nr)
            *(float2*)&out[(size_t)(r0 + row + 8) * Dd + col] = make_float2(v.z + cc.x, v.w + cc.y);
    }
}

// ---------------- launch ----------------
extern "C" void kernel_launch(void* const* d_in, const int* in_sizes, int n_in,
                              void* d_out, int out_size) {
    const float* feats = (const float*)d_in[0];
    const int*   src   = (const int*)d_in[1];
    const int*   dst   = (const int*)d_in[2];
    const float* W0    = (const float*)d_in[3];
    const float* b0    = (const float*)d_in[4];
    const float* W1    = (const float*)d_in[5];
    const float* b1    = (const float*)d_in[6];
    const float* W2w   = (const float*)d_in[7];
    const float* b2    = (const float*)d_in[8];
    const float* fcW   = (const float*)d_in[9];
    const float* fcb   = (const float*)d_in[10];
    const float* gamma = (const float*)d_in[11];
    const float* beta  = (const float*)d_in[12];
    const float* q     = (const float*)d_in[13];
    float* out = (float*)d_out;

    prep<<<NBLK1 + GM_BLOCKS, 256>>>(src, dst, feats,
                                     fcW, W0, W1, W2w, fcb, b0, b1, b2);  // launch 1 (prep ∥ gmat)
    spmm<<<Nn / 16, 256>>>(0, 0, 1);                                      // launch 2
    spmm<<<Nn / 16, 256>>>(1, 1, 1);                                      // launch 3
    spmm<<<Nn / 16, 256>>>(0, 2, 0);                                      // launch 4
    statspost<<<STATS_BLOCKS, 384>>>(gamma, beta, q);                     // launch 5
    out_mma<<<(Nn + 63) / 64, 256>>>(out);                                // launch 6
}

// round 16
// speedup vs baseline: 1.2000x; 1.0062x over previous
#include <cuda_runtime.h>
#include <cuda_fp16.h>
#include <cstdint>

#define Nn   100000
#define Ee   1600000
#define Dd   64
#define HIDv 512
#define C3   192
#define NBLK1 ((Nn + 255) / 256)   // 391
#define STATS_BLOCKS 148
#define GM_BLOCKS 128
#define KT 32
#define PADS 36
#define CSRSZ (Ee + 8 * Nn)        // padded CSR capacity

// ---------------- device scratch ----------------
__device__ __align__(16) __half g_uah[(Nn + 1) * Dd];   // fp16 u ping (+ zero sentinel row)
__device__ __align__(16) __half g_ubh[(Nn + 1) * Dd];   // fp16 u pong (+ zero sentinel row)
__device__ __align__(16) __half g_Hh[(size_t)Nn * C3];  // fp16 H
__device__ float g_norm[Nn];
__device__ float g_norm2[Nn];
__device__ int   g_deg[Nn];
__device__ int   g_rowptr[Nn + 1];
__device__ int   g_cursor[Nn];
__device__ __align__(16) int g_csr[CSRSZ];
__device__ int   g_bsum[512];
__device__ int   g_barcnt[8];
__device__ __align__(16) float g_G[HIDv * C3];
__device__ float g_bterm[HIDv];
__device__ __align__(16) float g_Cpart[(size_t)STATS_BLOCKS * C3 * C3];
__device__ float g_mHpart[STATS_BLOCKS * C3];
__device__ __align__(16) float g_Cmat[C3 * C3];
__device__ float g_mH[C3];
__device__ float g_scale[HIDv];
__device__ float g_shift[HIDv];
__device__ __align__(16) float g_W2[C3 * Dd];
__device__ __align__(16) float g_c0[Dd];

__device__ __forceinline__ float tf32r(float x) {
    uint32_t u;
    asm("cvt.rna.tf32.f32 %0, %1;" : "=r"(u) : "f"(x));
    return __uint_as_float(u);
}
__device__ __forceinline__ uint32_t f2u(float x) { return __float_as_uint(x); }

__device__ __forceinline__ void mma_tf32(float4& d, uint32_t a0, uint32_t a1, uint32_t a2, uint32_t a3,
                                         uint32_t b0, uint32_t b1) {
    asm volatile(
        "mma.sync.aligned.m16n8k8.row.col.f32.tf32.tf32.f32 "
        "{%0,%1,%2,%3}, {%4,%5,%6,%7}, {%8,%9}, {%0,%1,%2,%3};"
        : "+f"(d.x), "+f"(d.y), "+f"(d.z), "+f"(d.w)
        : "r"(a0), "r"(a1), "r"(a2), "r"(a3), "r"(b0), "r"(b1));
}

// software global barrier; all `target` blocks co-resident
__device__ __forceinline__ void gbarN(int k, int target) {
    __syncthreads();
    if (threadIdx.x == 0) {
        __threadfence();
        atomicAdd(&g_barcnt[k], 1);
        while (*(volatile int*)&g_barcnt[k] < target) { }
        __threadfence();
    }
    __syncthreads();
}

__device__ __forceinline__ void hillis256(int* sh, int t) {
#pragma unroll
    for (int off = 1; off < 256; off <<= 1) {
        int x = (t >= off) ? sh[t - off] : 0;
        __syncthreads();
        sh[t] += x;
        __syncthreads();
    }
}

// ---------------- kernel 1: blocks [0,391) prep; blocks [391,519) gmat+bterm ----------------
__global__ __launch_bounds__(256) void prep(const int* __restrict__ src,
                                            const int* __restrict__ dst,
                                            const float* __restrict__ feats,
                                            const float* __restrict__ fcW,
                                            const float* __restrict__ w0,
                                            const float* __restrict__ w1,
                                            const float* __restrict__ w2,
                                            const float* __restrict__ fcb,
                                            const float* __restrict__ b0,
                                            const float* __restrict__ b1,
                                            const float* __restrict__ b2) {
    int t = threadIdx.x;

    if (blockIdx.x >= NBLK1) {
        // ---- gmat + bterm for 4 h-rows (independent; overlaps prep) ----
        __shared__ float fw[4 * 1536];
        __shared__ float red[256];
        int hb = (blockIdx.x - NBLK1) * 4;
        for (int i = t; i < 4 * 1536; i += 256)
            fw[i] = fcW[(size_t)hb * 1536 + i];
        __syncthreads();
        for (int i = t; i < 4 * 192; i += 256) {
            int hl = i / 192, c = i % 192, j = c >> 6, d = c & 63;
            const float* W = (j == 0) ? w0 : (j == 1) ? w1 : w2;
            const float* f = fw + hl * 1536 + j * 512;
            float acc = 0.f;
#pragma unroll 8
            for (int m = 0; m < 512; m++) acc = fmaf(f[m], W[m * 64 + d], acc);
            g_G[(hb + hl) * C3 + c] = acc;
        }
        for (int r = 0; r < 4; r++) {
            float p = 0.f;
            for (int m = t; m < 1536; m += 256) {
                float bv = (m < 512) ? b0[m] : (m < 1024) ? b1[m - 512] : b2[m - 1024];
                p = fmaf(fw[r * 1536 + m], bv, p);
            }
            red[t] = p;
            __syncthreads();
            for (int s = 128; s > 0; s >>= 1) {
                if (t < s) red[t] += red[t + s];
                __syncthreads();
            }
            if (t == 0) g_bterm[hb + r] = red[0] + fcb[hb + r];
            __syncthreads();
        }
        return;
    }

    // ---- graph preprocessing (391 blocks) ----
    __shared__ int sh[256];
    __shared__ float snorm[256];
    int b = blockIdx.x;
    int i = b * 256 + t;

    // phase Z: zero deg, sentinel-fill csr, zero sentinel u rows
    for (int idx = i; idx < Nn; idx += NBLK1 * 256) g_deg[idx] = 0;
    for (int idx = i; idx < CSRSZ; idx += NBLK1 * 256) g_csr[idx] = Nn;
    if (b == 0 && t < 64) {
        ((uint2*)g_uah)[Nn * 16 + (t & 15)] = make_uint2(0u, 0u);
        ((uint2*)g_ubh)[Nn * 16 + (t & 15)] = make_uint2(0u, 0u);
    }
    gbarN(0, NBLK1);

    // phase A0: degree histogram
    for (int e = i; e < Ee; e += NBLK1 * 256)
        atomicAdd(&g_deg[dst[e]], 1);
    gbarN(1, NBLK1);

    // phase A: block-local exclusive scan of PADDED degrees
    int v = (i < Nn) ? g_deg[i] : 0;
    int vp = (v + 7) & ~7;
    sh[t] = vp;
    __syncthreads();
    hillis256(sh, t);
    int excl = sh[t] - vp;
    if (t == 255) g_bsum[b] = sh[255];
    gbarN(2, NBLK1);

    // phase B: block 0 scans the 391 block sums
    if (b == 0) {
        int v1 = *(volatile int*)&g_bsum[t];
        sh[t] = v1;
        __syncthreads();
        hillis256(sh, t);
        int s1 = sh[t];
        int tot1 = sh[255];
        __syncthreads();
        int v2 = (t + 256 < NBLK1) ? *(volatile int*)&g_bsum[t + 256] : 0;
        sh[t] = v2;
        __syncthreads();
        hillis256(sh, t);
        int s2 = sh[t] + tot1;
        __syncthreads();
        g_bsum[t] = s1 - v1;
        if (t + 256 < NBLK1) g_bsum[t + 256] = s2 - v2;
    }
    gbarN(3, NBLK1);

    // phase C: finalize rowptr/cursor/norm, scale features -> fp16 u0
    int boff = *(volatile int*)&g_bsum[b];
    float nm = 0.f;
    if (i < Nn) {
        int r = excl + boff;
        g_rowptr[i] = r;
        g_cursor[i] = r;
        float f = (v < 1) ? 1.0f : (float)v;
        nm = rsqrtf(f);
        g_norm[i] = nm;
        g_norm2[i] = nm * nm;
        if (i == Nn - 1) g_rowptr[Nn] = r + vp;
    }
    snorm[t] = nm;
    __syncthreads();
    int base = b * 256;
    int nnode = min(256, Nn - base);
    if (nnode > 0) {
        const float4* f4 = (const float4*)feats;
        uint2* u2 = (uint2*)g_uah;
        for (int idx = t; idx < nnode * 16; idx += 256) {
            float4 vv = f4[(size_t)base * 16 + idx];
            float s = snorm[idx >> 4];
            __half2 h0 = __float22half2_rn(make_float2(vv.x * s, vv.y * s));
            __half2 h1 = __float22half2_rn(make_float2(vv.z * s, vv.w * s));
            uint2 w;
            w.x = *(uint32_t*)&h0;
            w.y = *(uint32_t*)&h1;
            u2[(size_t)base * 16 + idx] = w;
        }
    }
    gbarN(4, NBLK1);

    // phase D: CSR fill (pad slots keep sentinel Nn)
    for (int e = i; e < Ee; e += NBLK1 * 256) {
        int d = dst[e];
        int p = atomicAdd(&g_cursor[d], 1);
        g_csr[p] = src[e];
    }
}

// ---------------- SpMM: half-warp per node, int4 index loads, NO tail (padded CSR) ----------------
__device__ __forceinline__ void acc_h4(float4& a, uint2 v) {
    float2 lo = __half22float2(*(__half2*)&v.x);
    float2 hi = __half22float2(*(__half2*)&v.y);
    a.x += lo.x; a.y += lo.y; a.z += hi.x; a.w += hi.y;
}

__global__ __launch_bounds__(256) void spmm(int srcbuf, int jcol, int writeU) {
    int node = (blockIdx.x << 4) | (threadIdx.x >> 4);   // half-warp id
    int q = threadIdx.x & 15;                            // lane within half
    const uint2* __restrict__ uin = (const uint2*)(srcbuf ? g_ubh : g_uah);
    uint2* __restrict__ uout = (uint2*)(srcbuf ? g_uah : g_ubh);
    int beg = g_rowptr[node];
    int end = g_rowptr[node + 1];
    float4 accA = make_float4(0.f, 0.f, 0.f, 0.f);
    float4 accB = make_float4(0.f, 0.f, 0.f, 0.f);
    for (int i = beg; i < end; i += 8) {
        int4 ca = *(const int4*)(g_csr + i);        // broadcast LDG.128
        int4 cb = *(const int4*)(g_csr + i + 4);
        uint2 v0 = uin[ca.x * 16 + q];
        uint2 v1 = uin[ca.y * 16 + q];
        uint2 v2 = uin[ca.z * 16 + q];
        uint2 v3 = uin[ca.w * 16 + q];
        uint2 v4 = uin[cb.x * 16 + q];
        uint2 v5 = uin[cb.y * 16 + q];
        uint2 v6 = uin[cb.z * 16 + q];
        uint2 v7 = uin[cb.w * 16 + q];
        acc_h4(accA, v0); acc_h4(accA, v1); acc_h4(accA, v2); acc_h4(accA, v3);
        acc_h4(accB, v4); acc_h4(accB, v5); acc_h4(accB, v6); acc_h4(accB, v7);
    }
    accA.x += accB.x; accA.y += accB.y; accA.z += accB.z; accA.w += accB.w;
    float nm = g_norm[node];
    __half2 p0 = __float22half2_rn(make_float2(accA.x * nm, accA.y * nm));
    __half2 p1 = __float22half2_rn(make_float2(accA.z * nm, accA.w * nm));
    uint2 hw;
    hw.x = *(uint32_t*)&p0;
    hw.y = *(uint32_t*)&p1;
    ((uint2*)g_Hh)[(size_t)node * 48 + jcol * 16 + q] = hw;
    if (writeU) {
        float n2 = g_norm2[node];
        __half2 u0 = __float22half2_rn(make_float2(accA.x * n2, accA.y * n2));
        __half2 u1 = __float22half2_rn(make_float2(accA.z * n2, accA.w * n2));
        uint2 w;
        w.x = *(uint32_t*)&u0;
        w.y = *(uint32_t*)&u1;
        uout[node * 16 + q] = w;
    }
}

// ---------------- stats via tf32 mma + fused reduce/bnprep/w2c0 (148 blocks, 384 thr) ----------------
__global__ __launch_bounds__(384, 1) void statspost(const float* __restrict__ gamma,
                                                    const float* __restrict__ beta,
                                                    const float* __restrict__ q) {
    __shared__ float Hs[C3 * PADS];
    __shared__ float mred[384];
    __shared__ float gsh[4][C3];
    __shared__ float red[C3], red2[C3];

    int tid = threadIdx.x;
    int sb = blockIdx.x;
    int warp = tid >> 5, lane = tid & 31;
    int mg = warp >> 1, ng = warp & 1;
    int lr = lane >> 2, lc = lane & 3;

    float4 acc[2][12];
#pragma unroll
    for (int a = 0; a < 2; a++)
#pragma unroll
        for (int b = 0; b < 12; b++) acc[a][b] = make_float4(0.f, 0.f, 0.f, 0.f);
    float msum = 0.f;

    int cfix = tid % C3;
    int rbase = tid / C3;

    const int ntiles = Nn / KT;
    for (int tile = sb; tile < ntiles; tile += STATS_BLOCKS) {
        int r0 = tile * KT;
        __syncthreads();
#pragma unroll
        for (int i = 0; i < KT / 2; i++) {
            int r = rbase + 2 * i;
            float v = __half2float(g_Hh[(size_t)(r0 + r) * C3 + cfix]);
            Hs[cfix * PADS + r] = v;
            msum += v;
        }
        __syncthreads();
#pragma unroll
        for (int ks = 0; ks < KT / 8; ks++) {
            int k0 = ks * 8;
            uint32_t a[2][4];
#pragma unroll
            for (int mt = 0; mt < 2; mt++) {
                int m = mg * 32 + mt * 16;
                a[mt][0] = f2u(Hs[(m + lr) * PADS + k0 + lc]);
                a[mt][1] = f2u(Hs[(m + 8 + lr) * PADS + k0 + lc]);
                a[mt][2] = f2u(Hs[(m + lr) * PADS + k0 + lc + 4]);
                a[mt][3] = f2u(Hs[(m + 8 + lr) * PADS + k0 + lc + 4]);
            }
#pragma unroll
            for (int nt = 0; nt < 12; nt++) {
                int n = ng * 96 + nt * 8;
                uint32_t b0v = f2u(Hs[(n + lr) * PADS + k0 + lc]);
                uint32_t b1v = f2u(Hs[(n + lr) * PADS + k0 + lc + 4]);
                mma_tf32(acc[0][nt], a[0][0], a[0][1], a[0][2], a[0][3], b0v, b1v);
                mma_tf32(acc[1][nt], a[1][0], a[1][1], a[1][2], a[1][3], b0v, b1v);
            }
        }
    }

    float* cp = g_Cpart + (size_t)sb * (C3 * C3);
#pragma unroll
    for (int mt = 0; mt < 2; mt++)
#pragma unroll
        for (int nt = 0; nt < 12; nt++) {
            int row = mg * 32 + mt * 16 + lr;
            int col = ng * 96 + nt * 8 + 2 * lc;
            float4 v = acc[mt][nt];
            *(float2*)&cp[(size_t)row * C3 + col] = make_float2(v.x, v.y);
            *(float2*)&cp[(size_t)(row + 8) * C3 + col] = make_float2(v.z, v.w);
        }
    mred[tid] = msum;
    __syncthreads();
    if (tid < C3) g_mHpart[sb * C3 + tid] = mred[tid] + mred[tid + C3];

    gbarN(5, STATS_BLOCKS);

    // ---- phase 1: reduce partials ----
    const float invN = 1.0f / (float)Nn;
    int gt = sb * 384 + tid;
    for (int idx = gt; idx < C3 * C3; idx += STATS_BLOCKS * 384) {
        float s = 0.f;
        for (int p = 0; p < STATS_BLOCKS; p++) s += g_Cpart[(size_t)p * (C3 * C3) + idx];
        g_Cmat[idx] = s * invN;
    }
    if (sb == 0 && tid < C3) {
        float s = 0.f;
        for (int p = 0; p < STATS_BLOCKS; p++) s += g_mHpart[p * C3 + tid];
        g_mH[tid] = s * invN;
    }
    gbarN(6, STATS_BLOCKS);

    // ---- phase 2: bnprep (blocks 0..127, 4 h-rows each) ----
    if (sb < GM_BLOCKS) {
        int c = tid;
        int hb = sb * 4;
        if (c < C3) {
#pragma unroll
            for (int j = 0; j < 4; j++) gsh[j][c] = g_G[(hb + j) * C3 + c];
        }
        __syncthreads();
        float t0 = 0.f, t1 = 0.f, t2 = 0.f, t3 = 0.f, mh = 0.f;
        if (c < C3) {
            for (int cc = 0; cc < C3; cc++) {
                float cm = g_Cmat[cc * C3 + c];
                t0 = fmaf(cm, gsh[0][cc], t0);
                t1 = fmaf(cm, gsh[1][cc], t1);
                t2 = fmaf(cm, gsh[2][cc], t2);
                t3 = fmaf(cm, gsh[3][cc], t3);
            }
            mh = g_mH[c];
        }
        float ts[4] = {t0, t1, t2, t3};
#pragma unroll
        for (int j = 0; j < 4; j++) {
            __syncthreads();
            if (c < C3) {
                red[c]  = gsh[j][c] * ts[j];
                red2[c] = gsh[j][c] * mh;
            }
            __syncthreads();
            if (c < 64) {
                red[c]  += red[c + 64]  + red[c + 128];
                red2[c] += red2[c + 64] + red2[c + 128];
            }
            __syncthreads();
            for (int s = 32; s > 0; s >>= 1) {
                if (c < s) { red[c] += red[c + s]; red2[c] += red2[c + s]; }
                __syncthreads();
            }
            if (c == 0) {
                int h = hb + j;
                float quad = red[0], dot1 = red2[0], bt = g_bterm[h];
                float mu  = dot1 + bt;
                float ef2 = quad + 2.f * bt * dot1 + bt * bt;
                float var = ef2 - mu * mu;
                float sc  = rsqrtf(var + 1e-5f) * gamma[h];
                g_scale[h] = sc;
                g_shift[h] = beta[h] - mu * sc;
            }
        }
    }
    gbarN(7, STATS_BLOCKS);

    // ---- phase 3: w2c0 ----
    if (gt < C3 * Dd) {
        int o = gt & 63, cc = gt >> 6;
        float s = 0.f;
#pragma unroll
        for (int k = 0; k < 8; k++) {
            int h = k * 64 + o;
            s += q[k] * g_scale[h] * g_G[h * C3 + cc];
        }
        g_W2[cc * Dd + o] = tf32r(s);
    }
    if (gt < Dd) {
        float s = 0.f;
#pragma unroll
        for (int k = 0; k < 8; k++) {
            int h = k * 64 + gt;
            s += q[k] * (g_scale[h] * g_bterm[h] + g_shift[h]);
        }
        g_c0[gt] = s;
    }
}

// ---------------- out = H (Nx192, fp16) @ W2^T via tf32 mma ----------------
#define PH 68
#define PW 72
__global__ __launch_bounds__(256) void out_mma(float* __restrict__ out) {
    if (blockIdx.x == 0 && threadIdx.x < 8) g_barcnt[threadIdx.x] = 0;

    __shared__ float Hs[64 * PH];
    __shared__ float W2s[64 * PW];
    int tid = threadIdx.x;
    int warp = tid >> 5, lane = tid & 31;
    int mg = warp >> 1, ng = warp & 1;
    int lr = lane >> 2, lc = lane & 3;
    int r0 = blockIdx.x * 64;
    int nr = min(64, Nn - r0);

    float4 acc[4];
#pragma unroll
    for (int a = 0; a < 4; a++) acc[a] = make_float4(0.f, 0.f, 0.f, 0.f);

#pragma unroll
    for (int kc = 0; kc < 3; kc++) {
        __syncthreads();
#pragma unroll
        for (int i = 0; i < 4; i++) {
            int idx4 = tid + i * 256;
            int m = idx4 >> 4, k4 = (idx4 & 15) << 2;
            float4 v = make_float4(0.f, 0.f, 0.f, 0.f);
            if (m < nr) {
                uint2 hv = ((const uint2*)g_Hh)[((size_t)(r0 + m) * C3 + kc * 64 + k4) >> 2];
                float2 lo = __half22float2(*(__half2*)&hv.x);
                float2 hi = __half22float2(*(__half2*)&hv.y);
                v = make_float4(lo.x, lo.y, hi.x, hi.y);
            }
            *(float4*)&Hs[m * PH + k4] = v;
        }
#pragma unroll
        for (int i = 0; i < 4; i++) {
            int idx4 = tid + i * 256;
            int k = idx4 >> 4, n4 = (idx4 & 15) << 2;
            *(float4*)&W2s[k * PW + n4] = *(const float4*)&g_W2[(kc * 64 + k) * Dd + n4];
        }
        __syncthreads();
#pragma unroll
        for (int ks = 0; ks < 8; ks++) {
            int k0 = ks * 8;
            int m0 = mg * 16;
            uint32_t a0 = f2u(Hs[(m0 + lr) * PH + k0 + lc]);
            uint32_t a1 = f2u(Hs[(m0 + 8 + lr) * PH + k0 + lc]);
            uint32_t a2 = f2u(Hs[(m0 + lr) * PH + k0 + lc + 4]);
            uint32_t a3 = f2u(Hs[(m0 + 8 + lr) * PH + k0 + lc + 4]);
#pragma unroll
            for (int nt = 0; nt < 4; nt++) {
                int n0 = ng * 32 + nt * 8;
                uint32_t b0 = f2u(W2s[(k0 + lc) * PW + n0 + lr]);
                uint32_t b1 = f2u(W2s[(k0 + lc + 4) * PW + n0 + lr]);
                mma_tf32(acc[nt], a0, a1, a2, a3, b0, b1);
            }
        }
    }

#pragma unroll
    for (int nt = 0; nt < 4; nt++) {
        int row = mg * 16 + lr;
        int col = ng * 32 + nt * 8 + 2 * lc;
        float2 cc = *(const float2*)&g_c0[col];
        float4 v = acc[nt];
        if (row < nr)
            *(float2*)&out[(size_t)(r0 + row) * Dd + col] = make_float2(v.x + cc.x, v.y + cc.y);
        if (row + 8 < nr)
            *(float2*)&out[(size_t)(r0 + row + 8) * Dd + col] = make_float2(v.z + cc.x, v.w + cc.y);
    }
}

// ---------------- launch ----------------
extern "C" void kernel_launch(void* const* d_in, const int* in_sizes, int n_in,
                              void* d_out, int out_size) {
    const float* feats = (const float*)d_in[0];
    const int*   src   = (const int*)d_in[1];
    const int*   dst   = (const int*)d_in[2];
    const float* W0    = (const float*)d_in[3];
    const float* b0    = (const float*)d_in[4];
    const float* W1    = (const float*)d_in[5];
    const float* b1    = (const float*)d_in[6];
    const float* W2w   = (const float*)d_in[7];
    const float* b2    = (const float*)d_in[8];
    const float* fcW   = (const float*)d_in[9];
    const float* fcb   = (const float*)d_in[10];
    const float* gamma = (const float*)d_in[11];
    const float* beta  = (const float*)d_in[12];
    const float* q     = (const float*)d_in[13];
    float* out = (float*)d_out;

    prep<<<NBLK1 + GM_BLOCKS, 256>>>(src, dst, feats,
                                     fcW, W0, W1, W2w, fcb, b0, b1, b2);  // launch 1 (prep ∥ gmat)
    spmm<<<Nn / 16, 256>>>(0, 0, 1);                                      // launch 2
    spmm<<<Nn / 16, 256>>>(1, 1, 1);                                      // launch 3
    spmm<<<Nn / 16, 256>>>(0, 2, 0);                                      // launch 4
    statspost<<<STATS_BLOCKS, 384>>>(gamma, beta, q);                     // launch 5
    out_mma<<<(Nn + 63) / 64, 256>>>(out);                                // launch 6
}